// round 11
// baseline (speedup 1.0000x reference)
#include <cuda_runtime.h>
#include <cstdint>
#include <math.h>

#define BB 32
#define CC 512
#define DD 512
#define HH 8
#define DH 64
#define DFF 2048
#define KW 7
#define KKTOT (CC*KW)   // 3584
#define CD (CC*DD)      // 262144
#define WSZ (CC*CC*KW)  // 1835008
#define LNEPS 1e-6f

// ---------------- scratch ----------------
__device__ float g_qin[(size_t)BB*CD];
__device__ float g_q  [(size_t)BB*CD];
__device__ float g_k  [(size_t)BB*CD];
__device__ float g_v  [(size_t)BB*CD];
__device__ float g_h1 [(size_t)BB*CD];
__device__ float g_S  [(size_t)BB*HH*CC*CC];
// pre-split operand storage
__device__ float g_wh  [(size_t)5*WSZ];
__device__ float g_wl  [(size_t)5*WSZ];
__device__ float g_xh  [(size_t)BB*CD];
__device__ float g_xl  [(size_t)BB*CD];
__device__ float g_qinh[(size_t)BB*CD];
__device__ float g_qinl[(size_t)BB*CD];
__device__ float g_xnh [(size_t)BB*CD];
__device__ float g_xnl [(size_t)BB*CD];
__device__ float g_oh  [(size_t)BB*CD];
__device__ float g_ol  [(size_t)BB*CD];
__device__ float g_w1h [(size_t)DD*DFF];
__device__ float g_w1l [(size_t)DD*DFF];
__device__ float g_w2h [(size_t)DFF*DD];
__device__ float g_w2l [(size_t)DFF*DD];
__device__ float g_hnh [(size_t)BB*CD];
__device__ float g_hnl [(size_t)BB*CD];
__device__ float g_midh[(size_t)BB*CC*DFF];
__device__ float g_midl[(size_t)BB*CC*DFF];

// ===================== helpers =====================
__device__ __forceinline__ void mma_tf32(float* d, const uint32_t* a, const uint32_t* b) {
    asm volatile(
        "mma.sync.aligned.m16n8k8.row.col.f32.tf32.tf32.f32 "
        "{%0,%1,%2,%3}, {%4,%5,%6,%7}, {%8,%9}, {%0,%1,%2,%3};"
        : "+f"(d[0]), "+f"(d[1]), "+f"(d[2]), "+f"(d[3])
        : "r"(a[0]), "r"(a[1]), "r"(a[2]), "r"(a[3]), "r"(b[0]), "r"(b[1]));
}
__device__ __forceinline__ float2 split2(float x) {
    uint32_t h, l;
    asm("cvt.rna.tf32.f32 %0, %1;" : "=r"(h) : "f"(x));
    float lf = x - __uint_as_float(h);
    asm("cvt.rna.tf32.f32 %0, %1;" : "=r"(l) : "f"(lf));
    return make_float2(__uint_as_float(h), __uint_as_float(l));
}
__device__ __forceinline__ uint32_t smem_u32(const void* p) {
    uint32_t a;
    asm("{ .reg .u64 t; cvta.to.shared.u64 t, %1; cvt.u32.u64 %0, t; }" : "=r"(a) : "l"(p));
    return a;
}
#define CP_ASYNC16(dst_u32, src_ptr) \
    asm volatile("cp.async.ca.shared.global [%0], [%1], 16;" :: "r"(dst_u32), "l"(src_ptr) : "memory")
#define CP_COMMIT() asm volatile("cp.async.commit_group;" ::: "memory")
#define CP_WAIT0()  asm volatile("cp.async.wait_group 0;" ::: "memory")

// ============================================================================
// split prep
// ============================================================================
__global__ void split_arr(const float* __restrict__ s, float* __restrict__ h,
                          float* __restrict__ l, int n)
{
    int i = blockIdx.x * blockDim.x + threadIdx.x;
    const int stride = gridDim.x * blockDim.x;
    for (; i < n; i += stride) {
        float2 p = split2(s[i]);
        h[i] = p.x; l[i] = p.y;
    }
}

// ============================================================================
// Tensor-core tf32 GEMM, 3xTF32 split, ALL OPERANDS PRE-SPLIT IN GMEM.
// A via cp.async ([m][k] stride 36), B via LDG+STS ([k][n] stride 136, Bh/Bl).
// 256 thr, 8 warps of 64x32, CTA 128x128, KST 32.  Mainloop: LDS.32+HMMA only.
//   convMode=1: B[n,kk] = Xsplit[b, ci, n0+n+sh]; convMode=0: B[n,kk]=B[kk*ldb+n]
// outMode: 0 = fp32 Y; 1 = split Yh/Yl; 2 = fp32 Y AND split Yh/Yl.
// ============================================================================
#define SSTRA 36
#define SSTRB 136
#define OAH 0
#define OAL (128*SSTRA)          // 4608
#define OBH (2*128*SSTRA)        // 9216
#define OBL (OBH + 32*SSTRB)     // 13568
#define STAGE_WORDS (OBL + 32*SSTRB)   // 17920
#define MM_SMEM (2*STAGE_WORDS*4)      // 143360 B

__global__ __launch_bounds__(256)
void mm_tc(const float* __restrict__ Ah, const float* __restrict__ Al, int lda,
           const float* __restrict__ Bh, const float* __restrict__ Bl,
           int convMode, int ldb,
           const float* __restrict__ bias, int biasPerRow, int doRelu, float scale,
           float* __restrict__ Y, float* __restrict__ Yh, float* __restrict__ Yl,
           int outMode, int ldy, int Kdim,
           size_t bStrideB, size_t bStrideY)
{
    extern __shared__ float sm[];
    const int tid  = threadIdx.x;
    const int wid  = tid >> 5;
    const int lane = tid & 31;
    const int m0 = blockIdx.y * 128;
    const int n0 = blockIdx.x * 128;

    const float* Bhb = Bh + (size_t)blockIdx.z * bStrideB;
    const float* Blb = Bl + (size_t)blockIdx.z * bStrideB;

    const int mbase = (wid & 1) * 64;
    const int nbase = (wid >> 1) * 32;
    const int g = lane >> 2;
    const int l = lane & 3;

    float acc[4][4][4];
#pragma unroll
    for (int mt = 0; mt < 4; mt++)
#pragma unroll
        for (int nt = 0; nt < 4; nt++)
#pragma unroll
            for (int r = 0; r < 4; r++) acc[mt][nt][r] = 0.f;

    const int nst = Kdim / 32;
    const uint32_t smem_base = smem_u32(sm);

    float pbh[4][4], pbl[4][4];

#define CPA(kk0, buf) do { \
    const uint32_t sb = smem_base + (buf) * STAGE_WORDS * 4; \
    _Pragma("unroll") \
    for (int i = 0; i < 4; i++) { \
        const int c = i * 256 + tid; \
        const int m = c >> 3, kc = (c & 7) << 2; \
        const size_t goff = (size_t)(m0 + m) * lda + (kk0) + kc; \
        const uint32_t doff = (uint32_t)(m * SSTRA + kc) * 4; \
        CP_ASYNC16(sb + OAH * 4 + doff, Ah + goff); \
        CP_ASYNC16(sb + OAL * 4 + doff, Al + goff); \
    } } while (0)

#define LDG_B(kk0) do { \
    if (convMode) { \
        _Pragma("unroll") \
        for (int li = 0; li < 4; li++) { \
            const int f = li * 256 + tid; \
            const int k = f >> 5, nc4 = (f & 31) * 4; \
            const int kkg = (kk0) + k; \
            const int ci = kkg / KW; \
            const int sh = kkg - ci * KW - (KW - 1); \
            const size_t base = (size_t)ci * DD + n0 + nc4 + sh; \
            const int p = n0 + nc4 + sh; \
            _Pragma("unroll") \
            for (int e = 0; e < 4; e++) { \
                const bool ok = (p + e >= 0); \
                pbh[li][e] = ok ? Bhb[base + e] : 0.f; \
                pbl[li][e] = ok ? Blb[base + e] : 0.f; \
            } \
        } \
    } else { \
        _Pragma("unroll") \
        for (int li = 0; li < 4; li++) { \
            const int f = li * 256 + tid; \
            const int k = f >> 5, nc4 = (f & 31) * 4; \
            const size_t base = (size_t)((kk0) + k) * ldb + n0 + nc4; \
            const float4 vh = *(const float4*)&Bhb[base]; \
            const float4 vl = *(const float4*)&Blb[base]; \
            pbh[li][0] = vh.x; pbh[li][1] = vh.y; pbh[li][2] = vh.z; pbh[li][3] = vh.w; \
            pbl[li][0] = vl.x; pbl[li][1] = vl.y; pbl[li][2] = vl.z; pbl[li][3] = vl.w; \
        } \
    } } while (0)

#define STS_B(buf) do { \
    float* sBh = sm + (buf) * STAGE_WORDS + OBH; \
    float* sBl = sm + (buf) * STAGE_WORDS + OBL; \
    _Pragma("unroll") \
    for (int li = 0; li < 4; li++) { \
        const int f = li * 256 + tid; \
        const int k = f >> 5, nc4 = (f & 31) * 4; \
        *(float4*)&sBh[k * SSTRB + nc4] = make_float4(pbh[li][0], pbh[li][1], pbh[li][2], pbh[li][3]); \
        *(float4*)&sBl[k * SSTRB + nc4] = make_float4(pbl[li][0], pbl[li][1], pbl[li][2], pbl[li][3]); \
    } } while (0)

    // prologue
    CPA(0, 0);
    CP_COMMIT();
    LDG_B(0);
    STS_B(0);
    CP_WAIT0();
    __syncthreads();

    for (int s = 0; s < nst; s++) {
        const int buf = s & 1;
        const bool hasNext = (s + 1) < nst;
        if (hasNext) {
            CPA((s + 1) * 32, buf ^ 1);
            CP_COMMIT();
            LDG_B((s + 1) * 32);
        }

        const float* sAh = sm + buf * STAGE_WORDS + OAH;
        const float* sAl = sm + buf * STAGE_WORDS + OAL;
        const float* sBh = sm + buf * STAGE_WORDS + OBH;
        const float* sBl = sm + buf * STAGE_WORDS + OBL;

#pragma unroll
        for (int k8 = 0; k8 < 32; k8 += 8) {
            uint32_t bh[4][2], bl[4][2];
#pragma unroll
            for (int nt = 0; nt < 4; nt++) {
                const int n = nbase + nt * 8 + g;
                bh[nt][0] = __float_as_uint(sBh[(k8 + l) * SSTRB + n]);
                bh[nt][1] = __float_as_uint(sBh[(k8 + 4 + l) * SSTRB + n]);
                bl[nt][0] = __float_as_uint(sBl[(k8 + l) * SSTRB + n]);
                bl[nt][1] = __float_as_uint(sBl[(k8 + 4 + l) * SSTRB + n]);
            }
#pragma unroll
            for (int mt = 0; mt < 4; mt++) {
                const int mr = (mbase + mt * 16 + g) * SSTRA;
                uint32_t ah[4], al[4];
                ah[0] = __float_as_uint(sAh[mr + k8 + l]);
                ah[1] = __float_as_uint(sAh[mr + 8 * SSTRA + k8 + l]);
                ah[2] = __float_as_uint(sAh[mr + k8 + 4 + l]);
                ah[3] = __float_as_uint(sAh[mr + 8 * SSTRA + k8 + 4 + l]);
                al[0] = __float_as_uint(sAl[mr + k8 + l]);
                al[1] = __float_as_uint(sAl[mr + 8 * SSTRA + k8 + l]);
                al[2] = __float_as_uint(sAl[mr + k8 + 4 + l]);
                al[3] = __float_as_uint(sAl[mr + 8 * SSTRA + k8 + 4 + l]);
#pragma unroll
                for (int nt = 0; nt < 4; nt++) mma_tf32(acc[mt][nt], ah, bh[nt]);
#pragma unroll
                for (int nt = 0; nt < 4; nt++) mma_tf32(acc[mt][nt], ah, bl[nt]);
#pragma unroll
                for (int nt = 0; nt < 4; nt++) mma_tf32(acc[mt][nt], al, bh[nt]);
            }
        }
        __syncthreads();
        if (hasNext) {
            STS_B(buf ^ 1);
            CP_WAIT0();
            __syncthreads();
        }
    }

    // -------- epilogue --------
    float* Yb  = (outMode != 1) ? (Y  + (size_t)blockIdx.z * bStrideY) : nullptr;
    float* Yhb = (outMode >= 1) ? (Yh + (size_t)blockIdx.z * bStrideY) : nullptr;
    float* Ylb = (outMode >= 1) ? (Yl + (size_t)blockIdx.z * bStrideY) : nullptr;
#pragma unroll
    for (int mt = 0; mt < 4; mt++) {
        const int r0 = m0 + mbase + mt * 16 + g;
        const int r1 = r0 + 8;
        const float bm0 = biasPerRow ? bias[r0] : 0.f;
        const float bm1 = biasPerRow ? bias[r1] : 0.f;
#pragma unroll
        for (int nt = 0; nt < 4; nt++) {
            const int c = n0 + nbase + nt * 8 + l * 2;
            const float bc0 = biasPerRow ? 0.f : bias[c];
            const float bc1 = biasPerRow ? 0.f : bias[c + 1];
            float v0 = acc[mt][nt][0] + (biasPerRow ? bm0 : bc0);
            float v1 = acc[mt][nt][1] + (biasPerRow ? bm0 : bc1);
            float v2 = acc[mt][nt][2] + (biasPerRow ? bm1 : bc0);
            float v3 = acc[mt][nt][3] + (biasPerRow ? bm1 : bc1);
            if (doRelu) {
                v0 = fmaxf(v0, 0.f); v1 = fmaxf(v1, 0.f);
                v2 = fmaxf(v2, 0.f); v3 = fmaxf(v3, 0.f);
            }
            v0 *= scale; v1 *= scale; v2 *= scale; v3 *= scale;
            if (outMode != 1) {
                *(float2*)&Yb[(size_t)r0 * ldy + c] = make_float2(v0, v1);
                *(float2*)&Yb[(size_t)r1 * ldy + c] = make_float2(v2, v3);
            }
            if (outMode >= 1) {
                float2 s0 = split2(v0), s1 = split2(v1), s2 = split2(v2), s3 = split2(v3);
                Yhb[(size_t)r0 * ldy + c]     = s0.x;  Ylb[(size_t)r0 * ldy + c]     = s0.y;
                Yhb[(size_t)r0 * ldy + c + 1] = s1.x;  Ylb[(size_t)r0 * ldy + c + 1] = s1.y;
                Yhb[(size_t)r1 * ldy + c]     = s2.x;  Ylb[(size_t)r1 * ldy + c]     = s2.y;
                Yhb[(size_t)r1 * ldy + c + 1] = s3.x;  Ylb[(size_t)r1 * ldy + c + 1] = s3.y;
            }
        }
    }
#undef CPA
#undef LDG_B
#undef STS_B
}

// ============================================================================
// QK^T (SIMT)
// ============================================================================
__global__ __launch_bounds__(256)
void qk_gemm(const float* __restrict__ Q, const float* __restrict__ Kt,
             float* __restrict__ S)
{
    const int z = blockIdx.z, b = z >> 3, h = z & 7;
    const int m0 = blockIdx.y * 128;
    const int n0 = blockIdx.x * 128;
    const float* Qb = Q  + (size_t)b * CD + h * DH;
    const float* Kb = Kt + (size_t)b * CD + h * DH;

    __shared__ float As[8][128];
    __shared__ float Bs[8][128];

    const int tid = threadIdx.x;
    const int tm = (tid >> 4) << 3;
    const int tn = (tid & 15) << 3;
    const int am = tid >> 1;
    const int ak = (tid & 1) << 2;

    float acc[8][8];
#pragma unroll
    for (int i = 0; i < 8; i++)
#pragma unroll
        for (int j = 0; j < 8; j++) acc[i][j] = 0.f;

    for (int kk0 = 0; kk0 < DH; kk0 += 8) {
        float4 a  = *(const float4*)&Qb[(size_t)(m0 + am) * DD + kk0 + ak];
        As[ak][am] = a.x; As[ak+1][am] = a.y; As[ak+2][am] = a.z; As[ak+3][am] = a.w;
        float4 bq = *(const float4*)&Kb[(size_t)(n0 + am) * DD + kk0 + ak];
        Bs[ak][am] = bq.x; Bs[ak+1][am] = bq.y; Bs[ak+2][am] = bq.z; Bs[ak+3][am] = bq.w;
        __syncthreads();
#pragma unroll
        for (int k = 0; k < 8; k++) {
            float4 a0 = *(const float4*)&As[k][tm];
            float4 a1 = *(const float4*)&As[k][tm + 4];
            float4 b0 = *(const float4*)&Bs[k][tn];
            float4 b1 = *(const float4*)&Bs[k][tn + 4];
            float av[8] = {a0.x,a0.y,a0.z,a0.w,a1.x,a1.y,a1.z,a1.w};
            float bv[8] = {b0.x,b0.y,b0.z,b0.w,b1.x,b1.y,b1.z,b1.w};
#pragma unroll
            for (int i = 0; i < 8; i++)
#pragma unroll
                for (int j = 0; j < 8; j++) acc[i][j] += av[i] * bv[j];
        }
        __syncthreads();
    }

    float* Sz = S + (size_t)z * CC * CC;
#pragma unroll
    for (int i = 0; i < 8; i++) {
        int m = m0 + tm + i;
        float4 o0 = make_float4(acc[i][0]*0.125f, acc[i][1]*0.125f, acc[i][2]*0.125f, acc[i][3]*0.125f);
        float4 o1 = make_float4(acc[i][4]*0.125f, acc[i][5]*0.125f, acc[i][6]*0.125f, acc[i][7]*0.125f);
        *(float4*)&Sz[(size_t)m * CC + n0 + tn]     = o0;
        *(float4*)&Sz[(size_t)m * CC + n0 + tn + 4] = o1;
    }
}

// ============================================================================
// Row softmax
// ============================================================================
__global__ __launch_bounds__(256)
void softmax_rows(float* __restrict__ S)
{
    const int warp = (blockIdx.x * blockDim.x + threadIdx.x) >> 5;
    const int lane = threadIdx.x & 31;
    float4* row = (float4*)(S + (size_t)warp * CC);

    float4 v[4];
    float mx = -1e30f;
#pragma unroll
    for (int i = 0; i < 4; i++) {
        v[i] = row[i * 32 + lane];
        mx = fmaxf(mx, fmaxf(fmaxf(v[i].x, v[i].y), fmaxf(v[i].z, v[i].w)));
    }
#pragma unroll
    for (int o = 16; o > 0; o >>= 1) mx = fmaxf(mx, __shfl_xor_sync(0xffffffffu, mx, o));

    float sum = 0.f;
#pragma unroll
    for (int i = 0; i < 4; i++) {
        v[i].x = expf(v[i].x - mx); v[i].y = expf(v[i].y - mx);
        v[i].z = expf(v[i].z - mx); v[i].w = expf(v[i].w - mx);
        sum += v[i].x + v[i].y + v[i].z + v[i].w;
    }
#pragma unroll
    for (int o = 16; o > 0; o >>= 1) sum += __shfl_xor_sync(0xffffffffu, sum, o);
    float inv = 1.f / sum;
#pragma unroll
    for (int i = 0; i < 4; i++) {
        v[i].x *= inv; v[i].y *= inv; v[i].z *= inv; v[i].w *= inv;
        row[i * 32 + lane] = v[i];
    }
}

// ============================================================================
// P @ V (SIMT), split output (hi/lo) for the conv_o B operand
// ============================================================================
__global__ __launch_bounds__(256)
void pv_gemm(const float* __restrict__ S, const float* __restrict__ V,
             float* __restrict__ Oh, float* __restrict__ Ol)
{
    const int z = blockIdx.z, b = z >> 3, h = z & 7;
    const int m0 = blockIdx.y * 128;
    const float* P  = S + (size_t)z * CC * CC;
    const float* Vb = V + (size_t)b * CD + h * DH;

    __shared__ float As[8][128];
    __shared__ float Bs[8][64];

    const int tid = threadIdx.x;
    const int tm = (tid >> 4) << 3;
    const int tn = (tid & 15) << 2;
    const int am = tid >> 1;
    const int ak = (tid & 1) << 2;
    const int bk = tid >> 5;
    const int bn = (tid & 31) << 1;

    float acc[8][4];
#pragma unroll
    for (int i = 0; i < 8; i++)
#pragma unroll
        for (int j = 0; j < 4; j++) acc[i][j] = 0.f;

    for (int kk0 = 0; kk0 < CC; kk0 += 8) {
        float4 a = *(const float4*)&P[(size_t)(m0 + am) * CC + kk0 + ak];
        As[ak][am] = a.x; As[ak+1][am] = a.y; As[ak+2][am] = a.z; As[ak+3][am] = a.w;
        float2 bv = *(const float2*)&Vb[(size_t)(kk0 + bk) * DD + bn];
        Bs[bk][bn] = bv.x; Bs[bk][bn + 1] = bv.y;
        __syncthreads();
#pragma unroll
        for (int k = 0; k < 8; k++) {
            float4 a0 = *(const float4*)&As[k][tm];
            float4 a1 = *(const float4*)&As[k][tm + 4];
            float4 b0 = *(const float4*)&Bs[k][tn];
            float av[8] = {a0.x,a0.y,a0.z,a0.w,a1.x,a1.y,a1.z,a1.w};
            float bv2[4] = {b0.x,b0.y,b0.z,b0.w};
#pragma unroll
            for (int i = 0; i < 8; i++)
#pragma unroll
                for (int j = 0; j < 4; j++) acc[i][j] += av[i] * bv2[j];
        }
        __syncthreads();
    }

    float* Ohb = Oh + (size_t)b * CD + h * DH;
    float* Olb = Ol + (size_t)b * CD + h * DH;
#pragma unroll
    for (int i = 0; i < 8; i++) {
        int m = m0 + tm + i;
        float2 s0 = split2(acc[i][0]), s1 = split2(acc[i][1]);
        float2 s2 = split2(acc[i][2]), s3 = split2(acc[i][3]);
        *(float4*)&Ohb[(size_t)m * DD + tn] = make_float4(s0.x, s1.x, s2.x, s3.x);
        *(float4*)&Olb[(size_t)m * DD + tn] = make_float4(s0.y, s1.y, s2.y, s3.y);
    }
}

// ============================================================================
// LayerNorm (torch-style). splitOut: write tf32 hi/lo instead of fp32.
// ============================================================================
__global__ __launch_bounds__(256)
void ln_kernel(const float* __restrict__ X, const float* __restrict__ g,
               const float* __restrict__ be, float* __restrict__ Y,
               float* __restrict__ Yh, float* __restrict__ Ylo, int splitOut)
{
    const int row  = (blockIdx.x * blockDim.x + threadIdx.x) >> 5;
    const int lane = threadIdx.x & 31;
    const float4* r = (const float4*)(X + (size_t)row * DD);

    float4 v[4];
    float s = 0.f;
#pragma unroll
    for (int i = 0; i < 4; i++) {
        v[i] = r[i * 32 + lane];
        s += v[i].x + v[i].y + v[i].z + v[i].w;
    }
#pragma unroll
    for (int off = 16; off > 0; off >>= 1) s += __shfl_xor_sync(0xffffffffu, s, off);
    float mean = s * (1.f / 512.f);

    float q = 0.f;
#pragma unroll
    for (int i = 0; i < 4; i++) {
        float dx = v[i].x - mean, dy = v[i].y - mean, dz = v[i].z - mean, dw = v[i].w - mean;
        q += dx*dx + dy*dy + dz*dz + dw*dw;
    }
#pragma unroll
    for (int off = 16; off > 0; off >>= 1) q += __shfl_xor_sync(0xffffffffu, q, off);
    float var = q * (1.f / 511.f);
    float inv = 1.f / (sqrtf(var) + LNEPS);

#pragma unroll
    for (int i = 0; i < 4; i++) {
        int d = (i * 32 + lane) * 4;
        float4 gg = *(const float4*)&g[d];
        float4 bb = *(const float4*)&be[d];
        float4 out;
        out.x = gg.x * (v[i].x - mean) * inv + bb.x;
        out.y = gg.y * (v[i].y - mean) * inv + bb.y;
        out.z = gg.z * (v[i].z - mean) * inv + bb.z;
        out.w = gg.w * (v[i].w - mean) * inv + bb.w;
        if (splitOut) {
            float2 s0 = split2(out.x), s1 = split2(out.y), s2 = split2(out.z), s3 = split2(out.w);
            const size_t idx = (size_t)row * DD + d;
            *(float4*)&Yh [idx] = make_float4(s0.x, s1.x, s2.x, s3.x);
            *(float4*)&Ylo[idx] = make_float4(s0.y, s1.y, s2.y, s3.y);
        } else {
            *(float4*)&Y[(size_t)row * DD + d] = out;
        }
    }
}

// ============================================================================
// Launch
// ============================================================================
extern "C" void kernel_launch(void* const* d_in, const int* in_sizes, int n_in,
                              void* d_out, int out_size)
{
    const float* x         = (const float*)d_in[0];
    const float* w_conv_in = (const float*)d_in[1];
    const float* b_conv_in = (const float*)d_in[2];
    const float* wq        = (const float*)d_in[3];
    const float* bq        = (const float*)d_in[4];
    const float* wk        = (const float*)d_in[5];
    const float* bk        = (const float*)d_in[6];
    const float* wv        = (const float*)d_in[7];
    const float* bv        = (const float*)d_in[8];
    const float* wo        = (const float*)d_in[9];
    const float* bo        = (const float*)d_in[10];
    const float* ln0_g     = (const float*)d_in[11];
    const float* ln0_b     = (const float*)d_in[12];
    const float* ln1_g     = (const float*)d_in[13];
    const float* ln1_b     = (const float*)d_in[14];
    const float* w1        = (const float*)d_in[15];
    const float* b1        = (const float*)d_in[16];
    const float* w2        = (const float*)d_in[17];
    const float* b2        = (const float*)d_in[18];
    float* out = (float*)d_out;

    float *qin, *q, *k, *v, *h1, *S;
    float *wh, *wl, *xh, *xl, *qinh, *qinl, *xnh, *xnl, *oh, *ol;
    float *w1h, *w1l, *w2h, *w2l, *hnh, *hnl, *midh, *midl;
    cudaGetSymbolAddress((void**)&qin, g_qin);
    cudaGetSymbolAddress((void**)&q,   g_q);
    cudaGetSymbolAddress((void**)&k,   g_k);
    cudaGetSymbolAddress((void**)&v,   g_v);
    cudaGetSymbolAddress((void**)&h1,  g_h1);
    cudaGetSymbolAddress((void**)&S,   g_S);
    cudaGetSymbolAddress((void**)&wh,  g_wh);
    cudaGetSymbolAddress((void**)&wl,  g_wl);
    cudaGetSymbolAddress((void**)&xh,  g_xh);
    cudaGetSymbolAddress((void**)&xl,  g_xl);
    cudaGetSymbolAddress((void**)&qinh, g_qinh);
    cudaGetSymbolAddress((void**)&qinl, g_qinl);
    cudaGetSymbolAddress((void**)&xnh, g_xnh);
    cudaGetSymbolAddress((void**)&xnl, g_xnl);
    cudaGetSymbolAddress((void**)&oh,  g_oh);
    cudaGetSymbolAddress((void**)&ol,  g_ol);
    cudaGetSymbolAddress((void**)&w1h, g_w1h);
    cudaGetSymbolAddress((void**)&w1l, g_w1l);
    cudaGetSymbolAddress((void**)&w2h, g_w2h);
    cudaGetSymbolAddress((void**)&w2l, g_w2l);
    cudaGetSymbolAddress((void**)&hnh, g_hnh);
    cudaGetSymbolAddress((void**)&hnl, g_hnl);
    cudaGetSymbolAddress((void**)&midh, g_midh);
    cudaGetSymbolAddress((void**)&midl, g_midl);

    cudaFuncSetAttribute(mm_tc, cudaFuncAttributeMaxDynamicSharedMemorySize, MM_SMEM);

    dim3 convGrid(4, 4, BB);
    const size_t cd = (size_t)CD;

    // 0. pre-split all static operands
    split_arr<<<1024, 256>>>(w_conv_in, wh + 0*(size_t)WSZ, wl + 0*(size_t)WSZ, WSZ);
    split_arr<<<1024, 256>>>(wq,        wh + 1*(size_t)WSZ, wl + 1*(size_t)WSZ, WSZ);
    split_arr<<<1024, 256>>>(wk,        wh + 2*(size_t)WSZ, wl + 2*(size_t)WSZ, WSZ);
    split_arr<<<1024, 256>>>(wv,        wh + 3*(size_t)WSZ, wl + 3*(size_t)WSZ, WSZ);
    split_arr<<<1024, 256>>>(wo,        wh + 4*(size_t)WSZ, wl + 4*(size_t)WSZ, WSZ);
    split_arr<<<2048, 256>>>(x,  xh,  xl,  BB * CD);
    split_arr<<<1024, 256>>>(w1, w1h, w1l, DD * DFF);
    split_arr<<<1024, 256>>>(w2, w2h, w2l, DFF * DD);

    // 1. query_in = conv(x)  -> fp32 (for LN0) + split (B of q-conv)
    mm_tc<<<convGrid, 256, MM_SMEM>>>(wh + 0*(size_t)WSZ, wl + 0*(size_t)WSZ, KKTOT,
                                      xh, xl, 1, DD, b_conv_in, 1, 0, 1.f,
                                      qin, qinh, qinl, 2, DD, KKTOT, cd, cd);
    // 2. xn = LN0(query_in) -> split only
    ln_kernel<<<2048, 256>>>(qin, ln0_g, ln0_b, nullptr, xnh, xnl, 1);
    // 3-5. q/k/v convs -> fp32 (SIMT attention consumes)
    mm_tc<<<convGrid, 256, MM_SMEM>>>(wh + 1*(size_t)WSZ, wl + 1*(size_t)WSZ, KKTOT,
                                      qinh, qinl, 1, DD, bq, 1, 0, 1.f,
                                      q, nullptr, nullptr, 0, DD, KKTOT, cd, cd);
    mm_tc<<<convGrid, 256, MM_SMEM>>>(wh + 2*(size_t)WSZ, wl + 2*(size_t)WSZ, KKTOT,
                                      xnh, xnl, 1, DD, bk, 1, 0, 1.f,
                                      k, nullptr, nullptr, 0, DD, KKTOT, cd, cd);
    mm_tc<<<convGrid, 256, MM_SMEM>>>(wh + 3*(size_t)WSZ, wl + 3*(size_t)WSZ, KKTOT,
                                      xnh, xnl, 1, DD, bv, 1, 0, 1.f,
                                      v, nullptr, nullptr, 0, DD, KKTOT, cd, cd);
    // 6. S = QK^T / 8
    qk_gemm<<<dim3(4, 4, BB * HH), 256>>>(q, k, S);
    // 7. softmax rows
    softmax_rows<<<16384, 256>>>(S);
    // 8. O = P V  -> split (B of conv_o)
    pv_gemm<<<dim3(1, 4, BB * HH), 256>>>(S, v, oh, ol);
    // 9. h1 = 2 * conv(o) -> fp32 (LN1 input)
    mm_tc<<<convGrid, 256, MM_SMEM>>>(wh + 4*(size_t)WSZ, wl + 4*(size_t)WSZ, KKTOT,
                                      oh, ol, 1, DD, bo, 1, 0, 2.f,
                                      h1, nullptr, nullptr, 0, DD, KKTOT, cd, cd);
    // 10. hn = LN1(h1) -> split
    ln_kernel<<<2048, 256>>>(h1, ln1_g, ln1_b, nullptr, hnh, hnl, 1);
    // 11. mid = relu(hn @ w1 + b1) -> split   M=16384 N=2048 K=512
    mm_tc<<<dim3(DFF / 128, (BB * CC) / 128, 1), 256, MM_SMEM>>>(
        hnh, hnl, DD, w1h, w1l, 0, DFF, b1, 0, 1, 1.f,
        nullptr, midh, midl, 1, DFF, DD, 0, 0);
    // 12. out = 2 * (mid @ w2 + b2) -> fp32   M=16384 N=512 K=2048
    mm_tc<<<dim3(DD / 128, (BB * CC) / 128, 1), 256, MM_SMEM>>>(
        midh, midl, DFF, w2h, w2l, 0, DD, b2, 0, 0, 2.f,
        out, nullptr, nullptr, 0, DD, DFF, 0, 0);
}

// round 12
// speedup vs baseline: 1.0456x; 1.0456x over previous
#include <cuda_runtime.h>
#include <cstdint>
#include <math.h>

#define BB 32
#define CC 512
#define DD 512
#define HH 8
#define DH 64
#define DFF 2048
#define KW 7
#define KKTOT (CC*KW)   // 3584
#define CD (CC*DD)      // 262144
#define WSZ (CC*CC*KW)  // 1835008
#define LNEPS 1e-6f

// ---------------- scratch ----------------
__device__ float g_qin[(size_t)BB*CD];
__device__ float g_xn [(size_t)BB*CD];
__device__ float g_q  [(size_t)BB*CD];
__device__ float g_k  [(size_t)BB*CD];
__device__ float g_v  [(size_t)BB*CD];
__device__ float g_o  [(size_t)BB*CD];
__device__ float g_h1 [(size_t)BB*CD];
__device__ float g_S  [(size_t)BB*HH*CC*CC];
// pre-split operand storage
__device__ float g_wh [(size_t)5*WSZ];
__device__ float g_wl [(size_t)5*WSZ];
__device__ float g_w1h[(size_t)DD*DFF];
__device__ float g_w1l[(size_t)DD*DFF];
__device__ float g_w2h[(size_t)DFF*DD];
__device__ float g_w2l[(size_t)DFF*DD];
__device__ float g_hnh[(size_t)BB*CD];
__device__ float g_hnl[(size_t)BB*CD];
__device__ float g_midh[(size_t)BB*CC*DFF];
__device__ float g_midl[(size_t)BB*CC*DFF];

// ===================== helpers =====================
__device__ __forceinline__ void mma_tf32(float* d, const uint32_t* a, const uint32_t* b) {
    asm volatile(
        "mma.sync.aligned.m16n8k8.row.col.f32.tf32.tf32.f32 "
        "{%0,%1,%2,%3}, {%4,%5,%6,%7}, {%8,%9}, {%0,%1,%2,%3};"
        : "+f"(d[0]), "+f"(d[1]), "+f"(d[2]), "+f"(d[3])
        : "r"(a[0]), "r"(a[1]), "r"(a[2]), "r"(a[3]), "r"(b[0]), "r"(b[1]));
}
__device__ __forceinline__ float2 split2(float x) {
    uint32_t h, l;
    asm("cvt.rna.tf32.f32 %0, %1;" : "=r"(h) : "f"(x));
    float lf = x - __uint_as_float(h);
    asm("cvt.rna.tf32.f32 %0, %1;" : "=r"(l) : "f"(lf));
    return make_float2(__uint_as_float(h), __uint_as_float(l));
}
__device__ __forceinline__ uint32_t smem_u32(const void* p) {
    uint32_t a;
    asm("{ .reg .u64 t; cvta.to.shared.u64 t, %1; cvt.u32.u64 %0, t; }" : "=r"(a) : "l"(p));
    return a;
}
#define CP_ASYNC16(dst_u32, src_ptr) \
    asm volatile("cp.async.ca.shared.global [%0], [%1], 16;" :: "r"(dst_u32), "l"(src_ptr) : "memory")
#define CP_COMMIT() asm volatile("cp.async.commit_group;" ::: "memory")
#define CP_WAIT0()  asm volatile("cp.async.wait_group 0;" ::: "memory")

// ============================================================================
// split prep: h[i],l[i] = tf32 split of s[i]
// ============================================================================
__global__ void split_arr(const float* __restrict__ s, float* __restrict__ h,
                          float* __restrict__ l, int n)
{
    int i = blockIdx.x * blockDim.x + threadIdx.x;
    const int stride = gridDim.x * blockDim.x;
    for (; i < n; i += stride) {
        float2 p = split2(s[i]);
        h[i] = p.x; l[i] = p.y;
    }
}

// ============================================================================
// Tensor-core tf32 GEMM, 3xTF32 split, A PRE-SPLIT IN GMEM (cp.async).
// B modes:
//   bMode=1 (conv): B[n,kk] = Bsrc[b, ci, n0+n+sh] raw fp32, split at STS
//   bMode=0 (dense raw): B[n,kk] = Bsrc[kk*ldb+n] raw fp32, split at STS
//   bMode=2 (dense pre-split): Bh=Bsrc, Bl=Bsrc2, float4 loads, STS direct
// 256 thr, 8 warps of 64x32, CTA 128x128, KST 32.  Mainloop: LDS.32+HMMA only.
// outSplit: write split2(result) to Yh/Yl instead of fp32 Y.
// ============================================================================
#define SSTRA 36
#define SSTRB 136
#define OAH 0
#define OAL (128*SSTRA)          // 4608
#define OBH (2*128*SSTRA)        // 9216
#define OBL (OBH + 32*SSTRB)     // 13568
#define STAGE_WORDS (OBL + 32*SSTRB)   // 17920
#define MM_SMEM (2*STAGE_WORDS*4)      // 143360 B

__global__ __launch_bounds__(256)
void mm_tc(const float* __restrict__ Ah, const float* __restrict__ Al, int lda,
           const float* __restrict__ Bsrc, const float* __restrict__ Bsrc2,
           int bMode, int ldb,
           const float* __restrict__ bias, int biasPerRow, int doRelu, float scale,
           float* __restrict__ Y, float* __restrict__ Yl, int outSplit, int ldy, int Kdim,
           size_t bStrideB, size_t bStrideY)
{
    extern __shared__ float sm[];
    const int tid  = threadIdx.x;
    const int wid  = tid >> 5;
    const int lane = tid & 31;
    const int m0 = blockIdx.y * 128;
    const int n0 = blockIdx.x * 128;

    const float* Bb  = Bsrc  + (size_t)blockIdx.z * bStrideB;
    const float* Bb2 = Bsrc2 ? (Bsrc2 + (size_t)blockIdx.z * bStrideB) : nullptr;

    const int mbase = (wid & 1) * 64;
    const int nbase = (wid >> 1) * 32;
    const int g = lane >> 2;
    const int l = lane & 3;

    float acc[4][4][4];
#pragma unroll
    for (int mt = 0; mt < 4; mt++)
#pragma unroll
        for (int nt = 0; nt < 4; nt++)
#pragma unroll
            for (int r = 0; r < 4; r++) acc[mt][nt][r] = 0.f;

    const int nst = Kdim / 32;
    const uint32_t smem_base = smem_u32(sm);

    float pbh[4][4];   // hi (or raw when bMode<2)
    float pbl[4][4];   // lo (bMode==2 only)

#define CPA(kk0, buf) do { \
    const uint32_t sb = smem_base + (buf) * STAGE_WORDS * 4; \
    _Pragma("unroll") \
    for (int i = 0; i < 4; i++) { \
        const int c = i * 256 + tid; \
        const int m = c >> 3, kc = (c & 7) << 2; \
        const size_t goff = (size_t)(m0 + m) * lda + (kk0) + kc; \
        const uint32_t doff = (uint32_t)(m * SSTRA + kc) * 4; \
        CP_ASYNC16(sb + OAH * 4 + doff, Ah + goff); \
        CP_ASYNC16(sb + OAL * 4 + doff, Al + goff); \
    } } while (0)

#define LDG_B(kk0) do { \
    if (bMode == 1) { \
        _Pragma("unroll") \
        for (int li = 0; li < 4; li++) { \
            const int f = li * 256 + tid; \
            const int k = f >> 5, nc4 = (f & 31) * 4; \
            const int kkg = (kk0) + k; \
            const int ci = kkg / KW; \
            const int sh = kkg - ci * KW - (KW - 1); \
            const float* src = Bb + (size_t)ci * DD + n0 + nc4 + sh; \
            const int p = n0 + nc4 + sh; \
            pbh[li][0] = (p + 0 >= 0) ? src[0] : 0.f; \
            pbh[li][1] = (p + 1 >= 0) ? src[1] : 0.f; \
            pbh[li][2] = (p + 2 >= 0) ? src[2] : 0.f; \
            pbh[li][3] = (p + 3 >= 0) ? src[3] : 0.f; \
        } \
    } else if (bMode == 0) { \
        _Pragma("unroll") \
        for (int li = 0; li < 4; li++) { \
            const int f = li * 256 + tid; \
            const int k = f >> 5, nc4 = (f & 31) * 4; \
            const float4 v = *(const float4*)&Bb[(size_t)((kk0) + k) * ldb + n0 + nc4]; \
            pbh[li][0] = v.x; pbh[li][1] = v.y; pbh[li][2] = v.z; pbh[li][3] = v.w; \
        } \
    } else { \
        _Pragma("unroll") \
        for (int li = 0; li < 4; li++) { \
            const int f = li * 256 + tid; \
            const int k = f >> 5, nc4 = (f & 31) * 4; \
            const size_t base = (size_t)((kk0) + k) * ldb + n0 + nc4; \
            const float4 vh = *(const float4*)&Bb[base]; \
            const float4 vl = *(const float4*)&Bb2[base]; \
            pbh[li][0] = vh.x; pbh[li][1] = vh.y; pbh[li][2] = vh.z; pbh[li][3] = vh.w; \
            pbl[li][0] = vl.x; pbl[li][1] = vl.y; pbl[li][2] = vl.z; pbl[li][3] = vl.w; \
        } \
    } } while (0)

#define STS_B(buf) do { \
    float* sBh = sm + (buf) * STAGE_WORDS + OBH; \
    float* sBl = sm + (buf) * STAGE_WORDS + OBL; \
    if (bMode == 2) { \
        _Pragma("unroll") \
        for (int li = 0; li < 4; li++) { \
            const int f = li * 256 + tid; \
            const int k = f >> 5, nc4 = (f & 31) * 4; \
            *(float4*)&sBh[k * SSTRB + nc4] = make_float4(pbh[li][0], pbh[li][1], pbh[li][2], pbh[li][3]); \
            *(float4*)&sBl[k * SSTRB + nc4] = make_float4(pbl[li][0], pbl[li][1], pbl[li][2], pbl[li][3]); \
        } \
    } else { \
        _Pragma("unroll") \
        for (int li = 0; li < 4; li++) { \
            const int f = li * 256 + tid; \
            const int k = f >> 5, nc4 = (f & 31) * 4; \
            float2 s0 = split2(pbh[li][0]); \
            float2 s1 = split2(pbh[li][1]); \
            float2 s2 = split2(pbh[li][2]); \
            float2 s3 = split2(pbh[li][3]); \
            *(float4*)&sBh[k * SSTRB + nc4] = make_float4(s0.x, s1.x, s2.x, s3.x); \
            *(float4*)&sBl[k * SSTRB + nc4] = make_float4(s0.y, s1.y, s2.y, s3.y); \
        } \
    } } while (0)

    // prologue
    CPA(0, 0);
    CP_COMMIT();
    LDG_B(0);
    STS_B(0);
    CP_WAIT0();
    __syncthreads();

    for (int s = 0; s < nst; s++) {
        const int buf = s & 1;
        const bool hasNext = (s + 1) < nst;
        if (hasNext) {
            CPA((s + 1) * 32, buf ^ 1);
            CP_COMMIT();
            LDG_B((s + 1) * 32);
        }

        const float* sAh = sm + buf * STAGE_WORDS + OAH;
        const float* sAl = sm + buf * STAGE_WORDS + OAL;
        const float* sBh = sm + buf * STAGE_WORDS + OBH;
        const float* sBl = sm + buf * STAGE_WORDS + OBL;

#pragma unroll
        for (int k8 = 0; k8 < 32; k8 += 8) {
            uint32_t bh[4][2], bl[4][2];
#pragma unroll
            for (int nt = 0; nt < 4; nt++) {
                const int n = nbase + nt * 8 + g;
                bh[nt][0] = __float_as_uint(sBh[(k8 + l) * SSTRB + n]);
                bh[nt][1] = __float_as_uint(sBh[(k8 + 4 + l) * SSTRB + n]);
                bl[nt][0] = __float_as_uint(sBl[(k8 + l) * SSTRB + n]);
                bl[nt][1] = __float_as_uint(sBl[(k8 + 4 + l) * SSTRB + n]);
            }
#pragma unroll
            for (int mt = 0; mt < 4; mt++) {
                const int mr = (mbase + mt * 16 + g) * SSTRA;
                uint32_t ah[4], al[4];
                ah[0] = __float_as_uint(sAh[mr + k8 + l]);
                ah[1] = __float_as_uint(sAh[mr + 8 * SSTRA + k8 + l]);
                ah[2] = __float_as_uint(sAh[mr + k8 + 4 + l]);
                ah[3] = __float_as_uint(sAh[mr + 8 * SSTRA + k8 + 4 + l]);
                al[0] = __float_as_uint(sAl[mr + k8 + l]);
                al[1] = __float_as_uint(sAl[mr + 8 * SSTRA + k8 + l]);
                al[2] = __float_as_uint(sAl[mr + k8 + 4 + l]);
                al[3] = __float_as_uint(sAl[mr + 8 * SSTRA + k8 + 4 + l]);
#pragma unroll
                for (int nt = 0; nt < 4; nt++) mma_tf32(acc[mt][nt], ah, bh[nt]);
#pragma unroll
                for (int nt = 0; nt < 4; nt++) mma_tf32(acc[mt][nt], ah, bl[nt]);
#pragma unroll
                for (int nt = 0; nt < 4; nt++) mma_tf32(acc[mt][nt], al, bh[nt]);
            }
        }
        __syncthreads();
        if (hasNext) {
            STS_B(buf ^ 1);
            CP_WAIT0();
            __syncthreads();
        }
    }

    // -------- epilogue --------
    float* Yb  = Y  + (size_t)blockIdx.z * bStrideY;
    float* Ylb = outSplit ? (Yl + (size_t)blockIdx.z * bStrideY) : nullptr;
#pragma unroll
    for (int mt = 0; mt < 4; mt++) {
        const int r0 = m0 + mbase + mt * 16 + g;
        const int r1 = r0 + 8;
        const float bm0 = biasPerRow ? bias[r0] : 0.f;
        const float bm1 = biasPerRow ? bias[r1] : 0.f;
#pragma unroll
        for (int nt = 0; nt < 4; nt++) {
            const int c = n0 + nbase + nt * 8 + l * 2;
            const float bc0 = biasPerRow ? 0.f : bias[c];
            const float bc1 = biasPerRow ? 0.f : bias[c + 1];
            float v0 = acc[mt][nt][0] + (biasPerRow ? bm0 : bc0);
            float v1 = acc[mt][nt][1] + (biasPerRow ? bm0 : bc1);
            float v2 = acc[mt][nt][2] + (biasPerRow ? bm1 : bc0);
            float v3 = acc[mt][nt][3] + (biasPerRow ? bm1 : bc1);
            if (doRelu) {
                v0 = fmaxf(v0, 0.f); v1 = fmaxf(v1, 0.f);
                v2 = fmaxf(v2, 0.f); v3 = fmaxf(v3, 0.f);
            }
            v0 *= scale; v1 *= scale; v2 *= scale; v3 *= scale;
            if (outSplit) {
                float2 s0 = split2(v0), s1 = split2(v1), s2 = split2(v2), s3 = split2(v3);
                Yb [(size_t)r0 * ldy + c]     = s0.x;  Ylb[(size_t)r0 * ldy + c]     = s0.y;
                Yb [(size_t)r0 * ldy + c + 1] = s1.x;  Ylb[(size_t)r0 * ldy + c + 1] = s1.y;
                Yb [(size_t)r1 * ldy + c]     = s2.x;  Ylb[(size_t)r1 * ldy + c]     = s2.y;
                Yb [(size_t)r1 * ldy + c + 1] = s3.x;  Ylb[(size_t)r1 * ldy + c + 1] = s3.y;
            } else {
                *(float2*)&Yb[(size_t)r0 * ldy + c] = make_float2(v0, v1);
                *(float2*)&Yb[(size_t)r1 * ldy + c] = make_float2(v2, v3);
            }
        }
    }
#undef CPA
#undef LDG_B
#undef STS_B
}

// ============================================================================
// QK^T (SIMT)
// ============================================================================
__global__ __launch_bounds__(256)
void qk_gemm(const float* __restrict__ Q, const float* __restrict__ Kt,
             float* __restrict__ S)
{
    const int z = blockIdx.z, b = z >> 3, h = z & 7;
    const int m0 = blockIdx.y * 128;
    const int n0 = blockIdx.x * 128;
    const float* Qb = Q  + (size_t)b * CD + h * DH;
    const float* Kb = Kt + (size_t)b * CD + h * DH;

    __shared__ float As[8][128];
    __shared__ float Bs[8][128];

    const int tid = threadIdx.x;
    const int tm = (tid >> 4) << 3;
    const int tn = (tid & 15) << 3;
    const int am = tid >> 1;
    const int ak = (tid & 1) << 2;

    float acc[8][8];
#pragma unroll
    for (int i = 0; i < 8; i++)
#pragma unroll
        for (int j = 0; j < 8; j++) acc[i][j] = 0.f;

    for (int kk0 = 0; kk0 < DH; kk0 += 8) {
        float4 a  = *(const float4*)&Qb[(size_t)(m0 + am) * DD + kk0 + ak];
        As[ak][am] = a.x; As[ak+1][am] = a.y; As[ak+2][am] = a.z; As[ak+3][am] = a.w;
        float4 bq = *(const float4*)&Kb[(size_t)(n0 + am) * DD + kk0 + ak];
        Bs[ak][am] = bq.x; Bs[ak+1][am] = bq.y; Bs[ak+2][am] = bq.z; Bs[ak+3][am] = bq.w;
        __syncthreads();
#pragma unroll
        for (int k = 0; k < 8; k++) {
            float4 a0 = *(const float4*)&As[k][tm];
            float4 a1 = *(const float4*)&As[k][tm + 4];
            float4 b0 = *(const float4*)&Bs[k][tn];
            float4 b1 = *(const float4*)&Bs[k][tn + 4];
            float av[8] = {a0.x,a0.y,a0.z,a0.w,a1.x,a1.y,a1.z,a1.w};
            float bv[8] = {b0.x,b0.y,b0.z,b0.w,b1.x,b1.y,b1.z,b1.w};
#pragma unroll
            for (int i = 0; i < 8; i++)
#pragma unroll
                for (int j = 0; j < 8; j++) acc[i][j] += av[i] * bv[j];
        }
        __syncthreads();
    }

    float* Sz = S + (size_t)z * CC * CC;
#pragma unroll
    for (int i = 0; i < 8; i++) {
        int m = m0 + tm + i;
        float4 o0 = make_float4(acc[i][0]*0.125f, acc[i][1]*0.125f, acc[i][2]*0.125f, acc[i][3]*0.125f);
        float4 o1 = make_float4(acc[i][4]*0.125f, acc[i][5]*0.125f, acc[i][6]*0.125f, acc[i][7]*0.125f);
        *(float4*)&Sz[(size_t)m * CC + n0 + tn]     = o0;
        *(float4*)&Sz[(size_t)m * CC + n0 + tn + 4] = o1;
    }
}

// ============================================================================
// Row softmax
// ============================================================================
__global__ __launch_bounds__(256)
void softmax_rows(float* __restrict__ S)
{
    const int warp = (blockIdx.x * blockDim.x + threadIdx.x) >> 5;
    const int lane = threadIdx.x & 31;
    float4* row = (float4*)(S + (size_t)warp * CC);

    float4 v[4];
    float mx = -1e30f;
#pragma unroll
    for (int i = 0; i < 4; i++) {
        v[i] = row[i * 32 + lane];
        mx = fmaxf(mx, fmaxf(fmaxf(v[i].x, v[i].y), fmaxf(v[i].z, v[i].w)));
    }
#pragma unroll
    for (int o = 16; o > 0; o >>= 1) mx = fmaxf(mx, __shfl_xor_sync(0xffffffffu, mx, o));

    float sum = 0.f;
#pragma unroll
    for (int i = 0; i < 4; i++) {
        v[i].x = expf(v[i].x - mx); v[i].y = expf(v[i].y - mx);
        v[i].z = expf(v[i].z - mx); v[i].w = expf(v[i].w - mx);
        sum += v[i].x + v[i].y + v[i].z + v[i].w;
    }
#pragma unroll
    for (int o = 16; o > 0; o >>= 1) sum += __shfl_xor_sync(0xffffffffu, sum, o);
    float inv = 1.f / sum;
#pragma unroll
    for (int i = 0; i < 4; i++) {
        v[i].x *= inv; v[i].y *= inv; v[i].z *= inv; v[i].w *= inv;
        row[i * 32 + lane] = v[i];
    }
}

// ============================================================================
// P @ V (SIMT)
// ============================================================================
__global__ __launch_bounds__(256)
void pv_gemm(const float* __restrict__ S, const float* __restrict__ V,
             float* __restrict__ O)
{
    const int z = blockIdx.z, b = z >> 3, h = z & 7;
    const int m0 = blockIdx.y * 128;
    const float* P  = S + (size_t)z * CC * CC;
    const float* Vb = V + (size_t)b * CD + h * DH;

    __shared__ float As[8][128];
    __shared__ float Bs[8][64];

    const int tid = threadIdx.x;
    const int tm = (tid >> 4) << 3;
    const int tn = (tid & 15) << 2;
    const int am = tid >> 1;
    const int ak = (tid & 1) << 2;
    const int bk = tid >> 5;
    const int bn = (tid & 31) << 1;

    float acc[8][4];
#pragma unroll
    for (int i = 0; i < 8; i++)
#pragma unroll
        for (int j = 0; j < 4; j++) acc[i][j] = 0.f;

    for (int kk0 = 0; kk0 < CC; kk0 += 8) {
        float4 a = *(const float4*)&P[(size_t)(m0 + am) * CC + kk0 + ak];
        As[ak][am] = a.x; As[ak+1][am] = a.y; As[ak+2][am] = a.z; As[ak+3][am] = a.w;
        float2 bv = *(const float2*)&Vb[(size_t)(kk0 + bk) * DD + bn];
        Bs[bk][bn] = bv.x; Bs[bk][bn + 1] = bv.y;
        __syncthreads();
#pragma unroll
        for (int k = 0; k < 8; k++) {
            float4 a0 = *(const float4*)&As[k][tm];
            float4 a1 = *(const float4*)&As[k][tm + 4];
            float4 b0 = *(const float4*)&Bs[k][tn];
            float av[8] = {a0.x,a0.y,a0.z,a0.w,a1.x,a1.y,a1.z,a1.w};
            float bv2[4] = {b0.x,b0.y,b0.z,b0.w};
#pragma unroll
            for (int i = 0; i < 8; i++)
#pragma unroll
                for (int j = 0; j < 4; j++) acc[i][j] += av[i] * bv2[j];
        }
        __syncthreads();
    }

    float* Ob = O + (size_t)b * CD + h * DH;
#pragma unroll
    for (int i = 0; i < 8; i++) {
        int m = m0 + tm + i;
        *(float4*)&Ob[(size_t)m * DD + tn] = make_float4(acc[i][0], acc[i][1], acc[i][2], acc[i][3]);
    }
}

// ============================================================================
// LayerNorm (torch-style). splitOut: write tf32 hi/lo instead of fp32.
// ============================================================================
__global__ __launch_bounds__(256)
void ln_kernel(const float* __restrict__ X, const float* __restrict__ g,
               const float* __restrict__ be, float* __restrict__ Y,
               float* __restrict__ Yh, float* __restrict__ Ylo, int splitOut)
{
    const int row  = (blockIdx.x * blockDim.x + threadIdx.x) >> 5;
    const int lane = threadIdx.x & 31;
    const float4* r = (const float4*)(X + (size_t)row * DD);

    float4 v[4];
    float s = 0.f;
#pragma unroll
    for (int i = 0; i < 4; i++) {
        v[i] = r[i * 32 + lane];
        s += v[i].x + v[i].y + v[i].z + v[i].w;
    }
#pragma unroll
    for (int off = 16; off > 0; off >>= 1) s += __shfl_xor_sync(0xffffffffu, s, off);
    float mean = s * (1.f / 512.f);

    float q = 0.f;
#pragma unroll
    for (int i = 0; i < 4; i++) {
        float dx = v[i].x - mean, dy = v[i].y - mean, dz = v[i].z - mean, dw = v[i].w - mean;
        q += dx*dx + dy*dy + dz*dz + dw*dw;
    }
#pragma unroll
    for (int off = 16; off > 0; off >>= 1) q += __shfl_xor_sync(0xffffffffu, q, off);
    float var = q * (1.f / 511.f);
    float inv = 1.f / (sqrtf(var) + LNEPS);

#pragma unroll
    for (int i = 0; i < 4; i++) {
        int d = (i * 32 + lane) * 4;
        float4 gg = *(const float4*)&g[d];
        float4 bb = *(const float4*)&be[d];
        float4 out;
        out.x = gg.x * (v[i].x - mean) * inv + bb.x;
        out.y = gg.y * (v[i].y - mean) * inv + bb.y;
        out.z = gg.z * (v[i].z - mean) * inv + bb.z;
        out.w = gg.w * (v[i].w - mean) * inv + bb.w;
        if (splitOut) {
            float2 s0 = split2(out.x), s1 = split2(out.y), s2 = split2(out.z), s3 = split2(out.w);
            const size_t idx = (size_t)row * DD + d;
            *(float4*)&Yh [idx] = make_float4(s0.x, s1.x, s2.x, s3.x);
            *(float4*)&Ylo[idx] = make_float4(s0.y, s1.y, s2.y, s3.y);
        } else {
            *(float4*)&Y[(size_t)row * DD + d] = out;
        }
    }
}

// ============================================================================
// Launch
// ============================================================================
extern "C" void kernel_launch(void* const* d_in, const int* in_sizes, int n_in,
                              void* d_out, int out_size)
{
    const float* x         = (const float*)d_in[0];
    const float* w_conv_in = (const float*)d_in[1];
    const float* b_conv_in = (const float*)d_in[2];
    const float* wq        = (const float*)d_in[3];
    const float* bq        = (const float*)d_in[4];
    const float* wk        = (const float*)d_in[5];
    const float* bk        = (const float*)d_in[6];
    const float* wv        = (const float*)d_in[7];
    const float* bv        = (const float*)d_in[8];
    const float* wo        = (const float*)d_in[9];
    const float* bo        = (const float*)d_in[10];
    const float* ln0_g     = (const float*)d_in[11];
    const float* ln0_b     = (const float*)d_in[12];
    const float* ln1_g     = (const float*)d_in[13];
    const float* ln1_b     = (const float*)d_in[14];
    const float* w1        = (const float*)d_in[15];
    const float* b1        = (const float*)d_in[16];
    const float* w2        = (const float*)d_in[17];
    const float* b2        = (const float*)d_in[18];
    float* out = (float*)d_out;

    float *qin, *xn, *q, *k, *v, *o, *h1, *S;
    float *wh, *wl, *w1h, *w1l, *w2h, *w2l, *hnh, *hnl, *midh, *midl;
    cudaGetSymbolAddress((void**)&qin, g_qin);
    cudaGetSymbolAddress((void**)&xn,  g_xn);
    cudaGetSymbolAddress((void**)&q,   g_q);
    cudaGetSymbolAddress((void**)&k,   g_k);
    cudaGetSymbolAddress((void**)&v,   g_v);
    cudaGetSymbolAddress((void**)&o,   g_o);
    cudaGetSymbolAddress((void**)&h1,  g_h1);
    cudaGetSymbolAddress((void**)&S,   g_S);
    cudaGetSymbolAddress((void**)&wh,  g_wh);
    cudaGetSymbolAddress((void**)&wl,  g_wl);
    cudaGetSymbolAddress((void**)&w1h, g_w1h);
    cudaGetSymbolAddress((void**)&w1l, g_w1l);
    cudaGetSymbolAddress((void**)&w2h, g_w2h);
    cudaGetSymbolAddress((void**)&w2l, g_w2l);
    cudaGetSymbolAddress((void**)&hnh, g_hnh);
    cudaGetSymbolAddress((void**)&hnl, g_hnl);
    cudaGetSymbolAddress((void**)&midh, g_midh);
    cudaGetSymbolAddress((void**)&midl, g_midl);

    cudaFuncSetAttribute(mm_tc, cudaFuncAttributeMaxDynamicSharedMemorySize, MM_SMEM);

    dim3 convGrid(4, 4, BB);
    const size_t cd = (size_t)CD;

    // 0. pre-split conv weights + FFN weights
    split_arr<<<1024, 256>>>(w_conv_in, wh + 0*(size_t)WSZ, wl + 0*(size_t)WSZ, WSZ);
    split_arr<<<1024, 256>>>(wq,        wh + 1*(size_t)WSZ, wl + 1*(size_t)WSZ, WSZ);
    split_arr<<<1024, 256>>>(wk,        wh + 2*(size_t)WSZ, wl + 2*(size_t)WSZ, WSZ);
    split_arr<<<1024, 256>>>(wv,        wh + 3*(size_t)WSZ, wl + 3*(size_t)WSZ, WSZ);
    split_arr<<<1024, 256>>>(wo,        wh + 4*(size_t)WSZ, wl + 4*(size_t)WSZ, WSZ);
    split_arr<<<1024, 256>>>(w1, w1h, w1l, DD * DFF);
    split_arr<<<1024, 256>>>(w2, w2h, w2l, DFF * DD);

    // 1. query_in = conv(x)
    mm_tc<<<convGrid, 256, MM_SMEM>>>(wh + 0*(size_t)WSZ, wl + 0*(size_t)WSZ, KKTOT,
                                      x, nullptr, 1, DD, b_conv_in, 1, 0, 1.f,
                                      qin, nullptr, 0, DD, KKTOT, cd, cd);
    // 2. xn = LN0(query_in)
    ln_kernel<<<2048, 256>>>(qin, ln0_g, ln0_b, xn, nullptr, nullptr, 0);
    // 3-5. q/k/v convs
    mm_tc<<<convGrid, 256, MM_SMEM>>>(wh + 1*(size_t)WSZ, wl + 1*(size_t)WSZ, KKTOT,
                                      qin, nullptr, 1, DD, bq, 1, 0, 1.f,
                                      q, nullptr, 0, DD, KKTOT, cd, cd);
    mm_tc<<<convGrid, 256, MM_SMEM>>>(wh + 2*(size_t)WSZ, wl + 2*(size_t)WSZ, KKTOT,
                                      xn, nullptr, 1, DD, bk, 1, 0, 1.f,
                                      k, nullptr, 0, DD, KKTOT, cd, cd);
    mm_tc<<<convGrid, 256, MM_SMEM>>>(wh + 3*(size_t)WSZ, wl + 3*(size_t)WSZ, KKTOT,
                                      xn, nullptr, 1, DD, bv, 1, 0, 1.f,
                                      v, nullptr, 0, DD, KKTOT, cd, cd);
    // 6. S = QK^T / 8
    qk_gemm<<<dim3(4, 4, BB * HH), 256>>>(q, k, S);
    // 7. softmax rows
    softmax_rows<<<16384, 256>>>(S);
    // 8. O = P V
    pv_gemm<<<dim3(1, 4, BB * HH), 256>>>(S, v, o);
    // 9. h1 = 2 * conv(o)
    mm_tc<<<convGrid, 256, MM_SMEM>>>(wh + 4*(size_t)WSZ, wl + 4*(size_t)WSZ, KKTOT,
                                      o, nullptr, 1, DD, bo, 1, 0, 2.f,
                                      h1, nullptr, 0, DD, KKTOT, cd, cd);
    // 10. hn = LN1(h1)  -> split output
    ln_kernel<<<2048, 256>>>(h1, ln1_g, ln1_b, nullptr, hnh, hnl, 1);
    // 11. mid = relu(hn @ w1 + b1)  -> split output   M=16384 N=2048 K=512
    mm_tc<<<dim3(DFF / 128, (BB * CC) / 128, 1), 256, MM_SMEM>>>(
        hnh, hnl, DD, w1h, w1l, 2, DFF, b1, 0, 1, 1.f,
        midh, midl, 1, DFF, DD, 0, 0);
    // 12. out = 2 * (mid @ w2 + b2)   M=16384 N=512 K=2048
    mm_tc<<<dim3(DD / 128, (BB * CC) / 128, 1), 256, MM_SMEM>>>(
        midh, midl, DFF, w2h, w2l, 2, DD, b2, 0, 0, 2.f,
        out, nullptr, 0, DD, DFF, 0, 0);
}

// round 13
// speedup vs baseline: 1.0967x; 1.0488x over previous
#include <cuda_runtime.h>
#include <cstdint>
#include <math.h>

#define BB 32
#define CC 512
#define DD 512
#define HH 8
#define DH 64
#define DFF 2048
#define KW 7
#define KKTOT (CC*KW)   // 3584
#define CD (CC*DD)      // 262144
#define WSZ (CC*CC*KW)  // 1835008
#define LNEPS 1e-6f

// ---------------- scratch ----------------
__device__ float g_qin[(size_t)BB*CD];
__device__ float g_xn [(size_t)BB*CD];
__device__ float g_q  [(size_t)BB*CD];
__device__ float g_k  [(size_t)BB*CD];
__device__ float g_v  [(size_t)BB*CD];
__device__ float g_o  [(size_t)BB*CD];
__device__ float g_h1 [(size_t)BB*CD];
__device__ float g_S  [(size_t)BB*HH*CC*CC];
// pre-split operand storage
__device__ float g_wh [(size_t)5*WSZ];
__device__ float g_wl [(size_t)5*WSZ];
__device__ float g_hnh[(size_t)BB*CD];
__device__ float g_hnl[(size_t)BB*CD];
__device__ float g_midh[(size_t)BB*CC*DFF];
__device__ float g_midl[(size_t)BB*CC*DFF];

// ===================== helpers =====================
__device__ __forceinline__ void mma_tf32(float* d, const uint32_t* a, const uint32_t* b) {
    asm volatile(
        "mma.sync.aligned.m16n8k8.row.col.f32.tf32.tf32.f32 "
        "{%0,%1,%2,%3}, {%4,%5,%6,%7}, {%8,%9}, {%0,%1,%2,%3};"
        : "+f"(d[0]), "+f"(d[1]), "+f"(d[2]), "+f"(d[3])
        : "r"(a[0]), "r"(a[1]), "r"(a[2]), "r"(a[3]), "r"(b[0]), "r"(b[1]));
}
__device__ __forceinline__ float2 split2(float x) {
    uint32_t h, l;
    asm("cvt.rna.tf32.f32 %0, %1;" : "=r"(h) : "f"(x));
    float lf = x - __uint_as_float(h);
    asm("cvt.rna.tf32.f32 %0, %1;" : "=r"(l) : "f"(lf));
    return make_float2(__uint_as_float(h), __uint_as_float(l));
}
__device__ __forceinline__ uint32_t smem_u32(const void* p) {
    uint32_t a;
    asm("{ .reg .u64 t; cvta.to.shared.u64 t, %1; cvt.u32.u64 %0, t; }" : "=r"(a) : "l"(p));
    return a;
}
#define CP_ASYNC16(dst_u32, src_ptr) \
    asm volatile("cp.async.ca.shared.global [%0], [%1], 16;" :: "r"(dst_u32), "l"(src_ptr) : "memory")
#define CP_COMMIT() asm volatile("cp.async.commit_group;" ::: "memory")
#define CP_WAIT0()  asm volatile("cp.async.wait_group 0;" ::: "memory")

// ============================================================================
// split prep (float4 vectorized)
// ============================================================================
__global__ void split_arr4(const float4* __restrict__ s, float4* __restrict__ h,
                           float4* __restrict__ l, int n4)
{
    int i = blockIdx.x * blockDim.x + threadIdx.x;
    const int stride = gridDim.x * blockDim.x;
    for (; i < n4; i += stride) {
        float4 v = s[i];
        float2 p0 = split2(v.x), p1 = split2(v.y), p2 = split2(v.z), p3 = split2(v.w);
        h[i] = make_float4(p0.x, p1.x, p2.x, p3.x);
        l[i] = make_float4(p0.y, p1.y, p2.y, p3.y);
    }
}

// ============================================================================
// Shared GEMM body macro: 3xTF32 split, A pre-split in GMEM (cp.async),
// B raw fp32 split at STS.  256 thr, 8 warps of 64x32, CTA 128x128, KST 32.
// ============================================================================
#define SSTRA 36
#define SSTRB 136
#define OAH 0
#define OAL (128*SSTRA)          // 4608
#define OBH (2*128*SSTRA)        // 9216
#define OBL (OBH + 32*SSTRB)     // 13568
#define STAGE_WORDS (OBL + 32*SSTRB)   // 17920
#define MM_SMEM (2*STAGE_WORDS*4)      // 143360 B

// The mainloop + epilogue shared by mm_tc and mm_tc_qkv.
// Expects in scope: sm, tid, wid, lane, m0, n0, Ah, Al, lda, Bb, convMode, ldb,
// bias, biasPerRow, doRelu, scale, YbPtr, YlbPtr, outSplit, ldy, Kdim.
#define GEMM_BODY() \
    const int mbase = (wid & 1) * 64; \
    const int nbase = (wid >> 1) * 32; \
    const int g = lane >> 2; \
    const int l = lane & 3; \
    float acc[4][4][4]; \
    _Pragma("unroll") \
    for (int mt = 0; mt < 4; mt++) \
        _Pragma("unroll") \
        for (int nt = 0; nt < 4; nt++) \
            _Pragma("unroll") \
            for (int r = 0; r < 4; r++) acc[mt][nt][r] = 0.f; \
    const int nst = Kdim / 32; \
    const uint32_t smem_base = smem_u32(sm); \
    float pb[4][4]; \
    /* prologue */ \
    CPA(0, 0); \
    CP_COMMIT(); \
    LDG_B(0); \
    STS_B(0); \
    CP_WAIT0(); \
    __syncthreads(); \
    for (int s = 0; s < nst; s++) { \
        const int buf = s & 1; \
        const bool hasNext = (s + 1) < nst; \
        if (hasNext) { \
            CPA((s + 1) * 32, buf ^ 1); \
            CP_COMMIT(); \
            LDG_B((s + 1) * 32); \
        } \
        const float* sAh = sm + buf * STAGE_WORDS + OAH; \
        const float* sAl = sm + buf * STAGE_WORDS + OAL; \
        const float* sBh = sm + buf * STAGE_WORDS + OBH; \
        const float* sBl = sm + buf * STAGE_WORDS + OBL; \
        _Pragma("unroll") \
        for (int k8 = 0; k8 < 32; k8 += 8) { \
            uint32_t bh[4][2], bl[4][2]; \
            _Pragma("unroll") \
            for (int nt = 0; nt < 4; nt++) { \
                const int n = nbase + nt * 8 + g; \
                bh[nt][0] = __float_as_uint(sBh[(k8 + l) * SSTRB + n]); \
                bh[nt][1] = __float_as_uint(sBh[(k8 + 4 + l) * SSTRB + n]); \
                bl[nt][0] = __float_as_uint(sBl[(k8 + l) * SSTRB + n]); \
                bl[nt][1] = __float_as_uint(sBl[(k8 + 4 + l) * SSTRB + n]); \
            } \
            _Pragma("unroll") \
            for (int mt = 0; mt < 4; mt++) { \
                const int mr = (mbase + mt * 16 + g) * SSTRA; \
                uint32_t ah[4], al[4]; \
                ah[0] = __float_as_uint(sAh[mr + k8 + l]); \
                ah[1] = __float_as_uint(sAh[mr + 8 * SSTRA + k8 + l]); \
                ah[2] = __float_as_uint(sAh[mr + k8 + 4 + l]); \
                ah[3] = __float_as_uint(sAh[mr + 8 * SSTRA + k8 + 4 + l]); \
                al[0] = __float_as_uint(sAl[mr + k8 + l]); \
                al[1] = __float_as_uint(sAl[mr + 8 * SSTRA + k8 + l]); \
                al[2] = __float_as_uint(sAl[mr + k8 + 4 + l]); \
                al[3] = __float_as_uint(sAl[mr + 8 * SSTRA + k8 + 4 + l]); \
                _Pragma("unroll") \
                for (int nt = 0; nt < 4; nt++) mma_tf32(acc[mt][nt], ah, bh[nt]); \
                _Pragma("unroll") \
                for (int nt = 0; nt < 4; nt++) mma_tf32(acc[mt][nt], ah, bl[nt]); \
                _Pragma("unroll") \
                for (int nt = 0; nt < 4; nt++) mma_tf32(acc[mt][nt], al, bh[nt]); \
            } \
        } \
        __syncthreads(); \
        if (hasNext) { \
            STS_B(buf ^ 1); \
            CP_WAIT0(); \
            __syncthreads(); \
        } \
    } \
    /* epilogue */ \
    _Pragma("unroll") \
    for (int mt = 0; mt < 4; mt++) { \
        const int r0 = m0 + mbase + mt * 16 + g; \
        const int r1 = r0 + 8; \
        const float bm0 = biasPerRow ? bias[r0] : 0.f; \
        const float bm1 = biasPerRow ? bias[r1] : 0.f; \
        _Pragma("unroll") \
        for (int nt = 0; nt < 4; nt++) { \
            const int c = n0 + nbase + nt * 8 + l * 2; \
            const float bc0 = biasPerRow ? 0.f : bias[c]; \
            const float bc1 = biasPerRow ? 0.f : bias[c + 1]; \
            float v0 = acc[mt][nt][0] + (biasPerRow ? bm0 : bc0); \
            float v1 = acc[mt][nt][1] + (biasPerRow ? bm0 : bc1); \
            float v2 = acc[mt][nt][2] + (biasPerRow ? bm1 : bc0); \
            float v3 = acc[mt][nt][3] + (biasPerRow ? bm1 : bc1); \
            if (doRelu) { \
                v0 = fmaxf(v0, 0.f); v1 = fmaxf(v1, 0.f); \
                v2 = fmaxf(v2, 0.f); v3 = fmaxf(v3, 0.f); \
            } \
            v0 *= scale; v1 *= scale; v2 *= scale; v3 *= scale; \
            if (outSplit) { \
                float2 s0 = split2(v0), s1 = split2(v1), s2 = split2(v2), s3 = split2(v3); \
                YbPtr [(size_t)r0 * ldy + c]     = s0.x;  YlbPtr[(size_t)r0 * ldy + c]     = s0.y; \
                YbPtr [(size_t)r0 * ldy + c + 1] = s1.x;  YlbPtr[(size_t)r0 * ldy + c + 1] = s1.y; \
                YbPtr [(size_t)r1 * ldy + c]     = s2.x;  YlbPtr[(size_t)r1 * ldy + c]     = s2.y; \
                YbPtr [(size_t)r1 * ldy + c + 1] = s3.x;  YlbPtr[(size_t)r1 * ldy + c + 1] = s3.y; \
            } else { \
                *(float2*)&YbPtr[(size_t)r0 * ldy + c] = make_float2(v0, v1); \
                *(float2*)&YbPtr[(size_t)r1 * ldy + c] = make_float2(v2, v3); \
            } \
        } \
    }

#define CPA(kk0, buf) do { \
    const uint32_t sb = smem_base + (buf) * STAGE_WORDS * 4; \
    _Pragma("unroll") \
    for (int i = 0; i < 4; i++) { \
        const int c = i * 256 + tid; \
        const int m = c >> 3, kc = (c & 7) << 2; \
        const size_t goff = (size_t)(m0 + m) * lda + (kk0) + kc; \
        const uint32_t doff = (uint32_t)(m * SSTRA + kc) * 4; \
        CP_ASYNC16(sb + OAH * 4 + doff, Ah + goff); \
        CP_ASYNC16(sb + OAL * 4 + doff, Al + goff); \
    } } while (0)

#define LDG_B(kk0) do { \
    if (convMode) { \
        _Pragma("unroll") \
        for (int li = 0; li < 4; li++) { \
            const int f = li * 256 + tid; \
            const int k = f >> 5, nc4 = (f & 31) * 4; \
            const int kkg = (kk0) + k; \
            const int ci = kkg / KW; \
            const int sh = kkg - ci * KW - (KW - 1); \
            const float* src = Bb + (size_t)ci * DD + n0 + nc4 + sh; \
            const int p = n0 + nc4 + sh; \
            pb[li][0] = (p + 0 >= 0) ? src[0] : 0.f; \
            pb[li][1] = (p + 1 >= 0) ? src[1] : 0.f; \
            pb[li][2] = (p + 2 >= 0) ? src[2] : 0.f; \
            pb[li][3] = (p + 3 >= 0) ? src[3] : 0.f; \
        } \
    } else { \
        _Pragma("unroll") \
        for (int li = 0; li < 4; li++) { \
            const int f = li * 256 + tid; \
            const int k = f >> 5, nc4 = (f & 31) * 4; \
            const float4 v = *(const float4*)&Bb[(size_t)((kk0) + k) * ldb + n0 + nc4]; \
            pb[li][0] = v.x; pb[li][1] = v.y; pb[li][2] = v.z; pb[li][3] = v.w; \
        } \
    } } while (0)

#define STS_B(buf) do { \
    float* sBh = sm + (buf) * STAGE_WORDS + OBH; \
    float* sBl = sm + (buf) * STAGE_WORDS + OBL; \
    _Pragma("unroll") \
    for (int li = 0; li < 4; li++) { \
        const int f = li * 256 + tid; \
        const int k = f >> 5, nc4 = (f & 31) * 4; \
        float2 s0 = split2(pb[li][0]); \
        float2 s1 = split2(pb[li][1]); \
        float2 s2 = split2(pb[li][2]); \
        float2 s3 = split2(pb[li][3]); \
        *(float4*)&sBh[k * SSTRB + nc4] = make_float4(s0.x, s1.x, s2.x, s3.x); \
        *(float4*)&sBl[k * SSTRB + nc4] = make_float4(s0.y, s1.y, s2.y, s3.y); \
    } } while (0)

// ============================================================================
// General GEMM (single source)
// ============================================================================
__global__ __launch_bounds__(256)
void mm_tc(const float* __restrict__ Ah, const float* __restrict__ Al, int lda,
           const float* __restrict__ Bsrc, int convMode, int ldb,
           const float* __restrict__ bias, int biasPerRow, int doRelu, float scale,
           float* __restrict__ Y, float* __restrict__ Yl, int outSplit, int ldy, int Kdim,
           size_t bStrideB, size_t bStrideY)
{
    extern __shared__ float sm[];
    const int tid  = threadIdx.x;
    const int wid  = tid >> 5;
    const int lane = tid & 31;
    const int m0 = blockIdx.y * 128;
    const int n0 = blockIdx.x * 128;
    const float* Bb = Bsrc + (size_t)blockIdx.z * bStrideB;
    float* YbPtr  = Y + (size_t)blockIdx.z * bStrideY;
    float* YlbPtr = outSplit ? (Yl + (size_t)blockIdx.z * bStrideY) : nullptr;
    GEMM_BODY()
}

// ============================================================================
// Merged q/k/v conv launch: grid (4,4,96).  zi = z>>5 selects operand set.
// ============================================================================
__global__ __launch_bounds__(256)
void mm_tc_qkv(const float* __restrict__ wh, const float* __restrict__ wl,
               const float* __restrict__ qin, const float* __restrict__ xn,
               const float* __restrict__ bq, const float* __restrict__ bk,
               const float* __restrict__ bv,
               float* __restrict__ qo, float* __restrict__ ko, float* __restrict__ vo)
{
    extern __shared__ float sm[];
    const int tid  = threadIdx.x;
    const int wid  = tid >> 5;
    const int lane = tid & 31;
    const int m0 = blockIdx.y * 128;
    const int n0 = blockIdx.x * 128;
    const int zi = blockIdx.z >> 5;        // 0=q, 1=k, 2=v
    const int b  = blockIdx.z & 31;

    const float* Ah = wh + (size_t)(zi + 1) * WSZ;   // wq/wk/wv at slots 1..3
    const float* Al = wl + (size_t)(zi + 1) * WSZ;
    const int lda = KKTOT;
    const float* Bb = ((zi == 0) ? qin : xn) + (size_t)b * CD;
    const float* bias = (zi == 0) ? bq : (zi == 1) ? bk : bv;
    float* YbPtr = ((zi == 0) ? qo : (zi == 1) ? ko : vo) + (size_t)b * CD;
    float* YlbPtr = nullptr;
    const int convMode = 1, ldb = DD, biasPerRow = 1, doRelu = 0, outSplit = 0;
    const float scale = 1.f;
    const int ldy = DD, Kdim = KKTOT;
    GEMM_BODY()
}

// ============================================================================
// QK^T (SIMT)
// ============================================================================
__global__ __launch_bounds__(256)
void qk_gemm(const float* __restrict__ Q, const float* __restrict__ Kt,
             float* __restrict__ S)
{
    const int z = blockIdx.z, b = z >> 3, h = z & 7;
    const int m0 = blockIdx.y * 128;
    const int n0 = blockIdx.x * 128;
    const float* Qb = Q  + (size_t)b * CD + h * DH;
    const float* Kb = Kt + (size_t)b * CD + h * DH;

    __shared__ float As[8][128];
    __shared__ float Bs[8][128];

    const int tid = threadIdx.x;
    const int tm = (tid >> 4) << 3;
    const int tn = (tid & 15) << 3;
    const int am = tid >> 1;
    const int ak = (tid & 1) << 2;

    float acc[8][8];
#pragma unroll
    for (int i = 0; i < 8; i++)
#pragma unroll
        for (int j = 0; j < 8; j++) acc[i][j] = 0.f;

    for (int kk0 = 0; kk0 < DH; kk0 += 8) {
        float4 a  = *(const float4*)&Qb[(size_t)(m0 + am) * DD + kk0 + ak];
        As[ak][am] = a.x; As[ak+1][am] = a.y; As[ak+2][am] = a.z; As[ak+3][am] = a.w;
        float4 bq = *(const float4*)&Kb[(size_t)(n0 + am) * DD + kk0 + ak];
        Bs[ak][am] = bq.x; Bs[ak+1][am] = bq.y; Bs[ak+2][am] = bq.z; Bs[ak+3][am] = bq.w;
        __syncthreads();
#pragma unroll
        for (int k = 0; k < 8; k++) {
            float4 a0 = *(const float4*)&As[k][tm];
            float4 a1 = *(const float4*)&As[k][tm + 4];
            float4 b0 = *(const float4*)&Bs[k][tn];
            float4 b1 = *(const float4*)&Bs[k][tn + 4];
            float av[8] = {a0.x,a0.y,a0.z,a0.w,a1.x,a1.y,a1.z,a1.w};
            float bv[8] = {b0.x,b0.y,b0.z,b0.w,b1.x,b1.y,b1.z,b1.w};
#pragma unroll
            for (int i = 0; i < 8; i++)
#pragma unroll
                for (int j = 0; j < 8; j++) acc[i][j] += av[i] * bv[j];
        }
        __syncthreads();
    }

    float* Sz = S + (size_t)z * CC * CC;
#pragma unroll
    for (int i = 0; i < 8; i++) {
        int m = m0 + tm + i;
        float4 o0 = make_float4(acc[i][0]*0.125f, acc[i][1]*0.125f, acc[i][2]*0.125f, acc[i][3]*0.125f);
        float4 o1 = make_float4(acc[i][4]*0.125f, acc[i][5]*0.125f, acc[i][6]*0.125f, acc[i][7]*0.125f);
        *(float4*)&Sz[(size_t)m * CC + n0 + tn]     = o0;
        *(float4*)&Sz[(size_t)m * CC + n0 + tn + 4] = o1;
    }
}

// ============================================================================
// Row softmax
// ============================================================================
__global__ __launch_bounds__(256)
void softmax_rows(float* __restrict__ S)
{
    const int warp = (blockIdx.x * blockDim.x + threadIdx.x) >> 5;
    const int lane = threadIdx.x & 31;
    float4* row = (float4*)(S + (size_t)warp * CC);

    float4 v[4];
    float mx = -1e30f;
#pragma unroll
    for (int i = 0; i < 4; i++) {
        v[i] = row[i * 32 + lane];
        mx = fmaxf(mx, fmaxf(fmaxf(v[i].x, v[i].y), fmaxf(v[i].z, v[i].w)));
    }
#pragma unroll
    for (int o = 16; o > 0; o >>= 1) mx = fmaxf(mx, __shfl_xor_sync(0xffffffffu, mx, o));

    float sum = 0.f;
#pragma unroll
    for (int i = 0; i < 4; i++) {
        v[i].x = expf(v[i].x - mx); v[i].y = expf(v[i].y - mx);
        v[i].z = expf(v[i].z - mx); v[i].w = expf(v[i].w - mx);
        sum += v[i].x + v[i].y + v[i].z + v[i].w;
    }
#pragma unroll
    for (int o = 16; o > 0; o >>= 1) sum += __shfl_xor_sync(0xffffffffu, sum, o);
    float inv = 1.f / sum;
#pragma unroll
    for (int i = 0; i < 4; i++) {
        v[i].x *= inv; v[i].y *= inv; v[i].z *= inv; v[i].w *= inv;
        row[i * 32 + lane] = v[i];
    }
}

// ============================================================================
// P @ V (SIMT)
// ============================================================================
__global__ __launch_bounds__(256)
void pv_gemm(const float* __restrict__ S, const float* __restrict__ V,
             float* __restrict__ O)
{
    const int z = blockIdx.z, b = z >> 3, h = z & 7;
    const int m0 = blockIdx.y * 128;
    const float* P  = S + (size_t)z * CC * CC;
    const float* Vb = V + (size_t)b * CD + h * DH;

    __shared__ float As[8][128];
    __shared__ float Bs[8][64];

    const int tid = threadIdx.x;
    const int tm = (tid >> 4) << 3;
    const int tn = (tid & 15) << 2;
    const int am = tid >> 1;
    const int ak = (tid & 1) << 2;
    const int bk = tid >> 5;
    const int bn = (tid & 31) << 1;

    float acc[8][4];
#pragma unroll
    for (int i = 0; i < 8; i++)
#pragma unroll
        for (int j = 0; j < 4; j++) acc[i][j] = 0.f;

    for (int kk0 = 0; kk0 < CC; kk0 += 8) {
        float4 a = *(const float4*)&P[(size_t)(m0 + am) * CC + kk0 + ak];
        As[ak][am] = a.x; As[ak+1][am] = a.y; As[ak+2][am] = a.z; As[ak+3][am] = a.w;
        float2 bv = *(const float2*)&Vb[(size_t)(kk0 + bk) * DD + bn];
        Bs[bk][bn] = bv.x; Bs[bk][bn + 1] = bv.y;
        __syncthreads();
#pragma unroll
        for (int k = 0; k < 8; k++) {
            float4 a0 = *(const float4*)&As[k][tm];
            float4 a1 = *(const float4*)&As[k][tm + 4];
            float4 b0 = *(const float4*)&Bs[k][tn];
            float av[8] = {a0.x,a0.y,a0.z,a0.w,a1.x,a1.y,a1.z,a1.w};
            float bv2[4] = {b0.x,b0.y,b0.z,b0.w};
#pragma unroll
            for (int i = 0; i < 8; i++)
#pragma unroll
                for (int j = 0; j < 4; j++) acc[i][j] += av[i] * bv2[j];
        }
        __syncthreads();
    }

    float* Ob = O + (size_t)b * CD + h * DH;
#pragma unroll
    for (int i = 0; i < 8; i++) {
        int m = m0 + tm + i;
        *(float4*)&Ob[(size_t)m * DD + tn] = make_float4(acc[i][0], acc[i][1], acc[i][2], acc[i][3]);
    }
}

// ============================================================================
// LayerNorm (torch-style). splitOut: write tf32 hi/lo instead of fp32.
// ============================================================================
__global__ __launch_bounds__(256)
void ln_kernel(const float* __restrict__ X, const float* __restrict__ g,
               const float* __restrict__ be, float* __restrict__ Y,
               float* __restrict__ Yh, float* __restrict__ Ylo, int splitOut)
{
    const int row  = (blockIdx.x * blockDim.x + threadIdx.x) >> 5;
    const int lane = threadIdx.x & 31;
    const float4* r = (const float4*)(X + (size_t)row * DD);

    float4 v[4];
    float s = 0.f;
#pragma unroll
    for (int i = 0; i < 4; i++) {
        v[i] = r[i * 32 + lane];
        s += v[i].x + v[i].y + v[i].z + v[i].w;
    }
#pragma unroll
    for (int off = 16; off > 0; off >>= 1) s += __shfl_xor_sync(0xffffffffu, s, off);
    float mean = s * (1.f / 512.f);

    float q = 0.f;
#pragma unroll
    for (int i = 0; i < 4; i++) {
        float dx = v[i].x - mean, dy = v[i].y - mean, dz = v[i].z - mean, dw = v[i].w - mean;
        q += dx*dx + dy*dy + dz*dz + dw*dw;
    }
#pragma unroll
    for (int off = 16; off > 0; off >>= 1) q += __shfl_xor_sync(0xffffffffu, q, off);
    float var = q * (1.f / 511.f);
    float inv = 1.f / (sqrtf(var) + LNEPS);

#pragma unroll
    for (int i = 0; i < 4; i++) {
        int d = (i * 32 + lane) * 4;
        float4 gg = *(const float4*)&g[d];
        float4 bb = *(const float4*)&be[d];
        float4 out;
        out.x = gg.x * (v[i].x - mean) * inv + bb.x;
        out.y = gg.y * (v[i].y - mean) * inv + bb.y;
        out.z = gg.z * (v[i].z - mean) * inv + bb.z;
        out.w = gg.w * (v[i].w - mean) * inv + bb.w;
        if (splitOut) {
            float2 s0 = split2(out.x), s1 = split2(out.y), s2 = split2(out.z), s3 = split2(out.w);
            const size_t idx = (size_t)row * DD + d;
            *(float4*)&Yh [idx] = make_float4(s0.x, s1.x, s2.x, s3.x);
            *(float4*)&Ylo[idx] = make_float4(s0.y, s1.y, s2.y, s3.y);
        } else {
            *(float4*)&Y[(size_t)row * DD + d] = out;
        }
    }
}

// ============================================================================
// Launch
// ============================================================================
extern "C" void kernel_launch(void* const* d_in, const int* in_sizes, int n_in,
                              void* d_out, int out_size)
{
    const float* x         = (const float*)d_in[0];
    const float* w_conv_in = (const float*)d_in[1];
    const float* b_conv_in = (const float*)d_in[2];
    const float* wq        = (const float*)d_in[3];
    const float* bq        = (const float*)d_in[4];
    const float* wk        = (const float*)d_in[5];
    const float* bk        = (const float*)d_in[6];
    const float* wv        = (const float*)d_in[7];
    const float* bv        = (const float*)d_in[8];
    const float* wo        = (const float*)d_in[9];
    const float* bo        = (const float*)d_in[10];
    const float* ln0_g     = (const float*)d_in[11];
    const float* ln0_b     = (const float*)d_in[12];
    const float* ln1_g     = (const float*)d_in[13];
    const float* ln1_b     = (const float*)d_in[14];
    const float* w1        = (const float*)d_in[15];
    const float* b1        = (const float*)d_in[16];
    const float* w2        = (const float*)d_in[17];
    const float* b2        = (const float*)d_in[18];
    float* out = (float*)d_out;

    float *qin, *xn, *q, *k, *v, *o, *h1, *S;
    float *wh, *wl, *hnh, *hnl, *midh, *midl;
    cudaGetSymbolAddress((void**)&qin, g_qin);
    cudaGetSymbolAddress((void**)&xn,  g_xn);
    cudaGetSymbolAddress((void**)&q,   g_q);
    cudaGetSymbolAddress((void**)&k,   g_k);
    cudaGetSymbolAddress((void**)&v,   g_v);
    cudaGetSymbolAddress((void**)&o,   g_o);
    cudaGetSymbolAddress((void**)&h1,  g_h1);
    cudaGetSymbolAddress((void**)&S,   g_S);
    cudaGetSymbolAddress((void**)&wh,  g_wh);
    cudaGetSymbolAddress((void**)&wl,  g_wl);
    cudaGetSymbolAddress((void**)&hnh, g_hnh);
    cudaGetSymbolAddress((void**)&hnl, g_hnl);
    cudaGetSymbolAddress((void**)&midh, g_midh);
    cudaGetSymbolAddress((void**)&midl, g_midl);

    cudaFuncSetAttribute(mm_tc, cudaFuncAttributeMaxDynamicSharedMemorySize, MM_SMEM);
    cudaFuncSetAttribute(mm_tc_qkv, cudaFuncAttributeMaxDynamicSharedMemorySize, MM_SMEM);

    dim3 convGrid(4, 4, BB);
    const size_t cd = (size_t)CD;

    // 0. pre-split conv weights (float4 vectorized)
    split_arr4<<<512, 256>>>((const float4*)w_conv_in, (float4*)(wh + 0*(size_t)WSZ),
                             (float4*)(wl + 0*(size_t)WSZ), WSZ / 4);
    split_arr4<<<512, 256>>>((const float4*)wq, (float4*)(wh + 1*(size_t)WSZ),
                             (float4*)(wl + 1*(size_t)WSZ), WSZ / 4);
    split_arr4<<<512, 256>>>((const float4*)wk, (float4*)(wh + 2*(size_t)WSZ),
                             (float4*)(wl + 2*(size_t)WSZ), WSZ / 4);
    split_arr4<<<512, 256>>>((const float4*)wv, (float4*)(wh + 3*(size_t)WSZ),
                             (float4*)(wl + 3*(size_t)WSZ), WSZ / 4);
    split_arr4<<<512, 256>>>((const float4*)wo, (float4*)(wh + 4*(size_t)WSZ),
                             (float4*)(wl + 4*(size_t)WSZ), WSZ / 4);

    // 1. query_in = conv(x)
    mm_tc<<<convGrid, 256, MM_SMEM>>>(wh + 0*(size_t)WSZ, wl + 0*(size_t)WSZ, KKTOT,
                                      x, 1, DD, b_conv_in, 1, 0, 1.f,
                                      qin, nullptr, 0, DD, KKTOT, cd, cd);
    // 2. xn = LN0(query_in)
    ln_kernel<<<2048, 256>>>(qin, ln0_g, ln0_b, xn, nullptr, nullptr, 0);
    // 3. merged q/k/v convs (1536 CTAs, one launch)
    mm_tc_qkv<<<dim3(4, 4, 3 * BB), 256, MM_SMEM>>>(wh, wl, qin, xn, bq, bk, bv, q, k, v);
    // 4. S = QK^T / 8
    qk_gemm<<<dim3(4, 4, BB * HH), 256>>>(q, k, S);
    // 5. softmax rows
    softmax_rows<<<16384, 256>>>(S);
    // 6. O = P V
    pv_gemm<<<dim3(1, 4, BB * HH), 256>>>(S, v, o);
    // 7. h1 = 2 * conv(o)
    mm_tc<<<convGrid, 256, MM_SMEM>>>(wh + 4*(size_t)WSZ, wl + 4*(size_t)WSZ, KKTOT,
                                      o, 1, DD, bo, 1, 0, 2.f,
                                      h1, nullptr, 0, DD, KKTOT, cd, cd);
    // 8. hn = LN1(h1)  -> split output
    ln_kernel<<<2048, 256>>>(h1, ln1_g, ln1_b, nullptr, hnh, hnl, 1);
    // 9. mid = relu(hn @ w1 + b1)  -> split output   M=16384 N=2048 K=512
    mm_tc<<<dim3(DFF / 128, (BB * CC) / 128, 1), 256, MM_SMEM>>>(
        hnh, hnl, DD, w1, 0, DFF, b1, 0, 1, 1.f,
        midh, midl, 1, DFF, DD, 0, 0);
    // 10. out = 2 * (mid @ w2 + b2)   M=16384 N=512 K=2048
    mm_tc<<<dim3(DD / 128, (BB * CC) / 128, 1), 256, MM_SMEM>>>(
        midh, midl, DFF, w2, 0, DD, b2, 0, 0, 2.f,
        out, nullptr, 0, DD, DFF, 0, 0);
}